// round 6
// baseline (speedup 1.0000x reference)
#include <cuda_runtime.h>
#include <cuda_fp16.h>

#define NI 2000      // inner tree nodes
#define NL 10000     // leaves / vocab
#define ND 128       // docs
#define PP 2048      // padded proj width
#define FC 64        // mass feature chunk
#define NMASS_CH 157 // ceil(NL/FC)
#define MP_BLKS (3 * NMASS_CH)   // 471 mass-pair blocks
#define SROWH 68     // half2 row stride per feature-pair
#define AG_BLKS 400  // argmax: 10 float4-col blocks x 40 row-chunks
#define AG_CH 50     // rows per argmax chunk
// proj-pair: 64x64 doc tiles, 32-feature chunks, 4x4 micro-tile
#define PFC 32
#define SROW4 68     // float row stride (float4-aligned, bank-skewed)
#define PP_BLKS (3 * (PP / PFC))   // 192

__device__ unsigned long long g_amax[NL];
__device__ float g_proj[ND * PP];
__device__ float g_S[ND];

__device__ __forceinline__ __half2 u2h2(unsigned u) {
    return *reinterpret_cast<__half2*>(&u);
}
__device__ __forceinline__ unsigned long long pack_key(float v, int idx) {
    unsigned u = __float_as_uint(v);
    u = (u & 0x80000000u) ? ~u : (u | 0x80000000u);
    return ((unsigned long long)u << 32) | (unsigned)idx;
}

// ---------------------------------------------------------------- init
__global__ void k_init(float* __restrict__ out) {
    int i = blockIdx.x * blockDim.x + threadIdx.x;
    if (i < NL) g_amax[i] = 0ull;
    if (i < ND * ND) out[i] = 0.0f;
    if (i < ND) g_S[i] = 0.0f;
}

// ---------------------------------------------------------------- column argmax of param (float4, 4 lane-chains)
__global__ void __launch_bounds__(256)
k_argmax(const float* __restrict__ param) {
    int bid = blockIdx.x;
    int j4 = (bid % 10) * 256 + threadIdx.x;    // float4 column
    if (j4 >= NL / 4) return;
    int r0 = (bid / 10) * AG_CH;
    const float4* p = (const float4*)param + (size_t)r0 * (NL / 4) + j4;
    float4 bv = p[0];
    int ix = r0, iy = r0, iz = r0, iw = r0;
    #pragma unroll 4
    for (int r = 1; r < AG_CH; r++) {
        float4 v = p[(size_t)r * (NL / 4)];
        if (v.x > bv.x) { bv.x = v.x; ix = r0 + r; }
        if (v.y > bv.y) { bv.y = v.y; iy = r0 + r; }
        if (v.z > bv.z) { bv.z = v.z; iz = r0 + r; }
        if (v.w > bv.w) { bv.w = v.w; iw = r0 + r; }
    }
    int j = 4 * j4;
    atomicMax(&g_amax[j + 0], pack_key(bv.x, ix));
    atomicMax(&g_amax[j + 1], pack_key(bv.y, iy));
    atomicMax(&g_amax[j + 2], pack_key(bv.z, iz));
    atomicMax(&g_amax[j + 3], pack_key(bv.w, iw));
}

// ---------------------------------------------------------------- fp16 mass-pair (64x64 tiles, 64-f chunks)
__global__ void __launch_bounds__(256)
k_masspair(const float* __restrict__ mass, float* __restrict__ out) {
    __shared__ __half2 sa2[32 * SROWH];
    __shared__ __half2 sb2[32 * SROWH];
    int pid = blockIdx.x;
    int tp = pid % 3;                 // 0:(0,0) 1:(0,1)+mirror 2:(1,1)
    int chunk = pid / 3;
    int fb = chunk * FC;
    int nh = min(FC, NL - fb) >> 1;   // valid half2 feature-pairs
    int it = (tp == 2) ? 1 : 0;
    int jt = (tp == 0) ? 0 : 1;
    int tid = threadIdx.x;

    const __half2 hz = __float2half2_rn(0.0f);
    #pragma unroll
    for (int k = 0; k < 8; k++) {
        int idx = tid + k * 256;          // 0..2047
        int f2 = idx & 31;
        int row = idx >> 5;               // 0..63
        __half2 ha = hz, hb = hz;
        if (f2 < nh) {
            float2 va = *(const float2*)&mass[(size_t)(it * 64 + row) * NL + fb + 2 * f2];
            float2 vb = *(const float2*)&mass[(size_t)(jt * 64 + row) * NL + fb + 2 * f2];
            ha = __floats2half2_rn(va.x, va.y);
            hb = __floats2half2_rn(vb.x, vb.y);
        }
        sa2[f2 * SROWH + row] = ha;
        sb2[f2 * SROWH + row] = hb;
    }
    __syncthreads();

    int tx = tid & 15, ty = tid >> 4;
    __half2 acc[4][4];
    #pragma unroll
    for (int r = 0; r < 4; r++)
        #pragma unroll
        for (int c = 0; c < 4; c++) acc[r][c] = hz;

    #pragma unroll 4
    for (int f2 = 0; f2 < 32; f2++) {
        uint4 ua = *(const uint4*)&sa2[f2 * SROWH + ty * 4];
        uint4 ub = *(const uint4*)&sb2[f2 * SROWH + tx * 4];
        __half2 ar[4] = {u2h2(ua.x), u2h2(ua.y), u2h2(ua.z), u2h2(ua.w)};
        __half2 br[4] = {u2h2(ub.x), u2h2(ub.y), u2h2(ub.z), u2h2(ub.w)};
        #pragma unroll
        for (int r = 0; r < 4; r++)
            #pragma unroll
            for (int c = 0; c < 4; c++)
                acc[r][c] = __hadd2(acc[r][c], __hmin2(ar[r], br[c]));
    }

    int ib = it * 64 + ty * 4, jb = jt * 64 + tx * 4;
    #pragma unroll
    for (int r = 0; r < 4; r++)
        #pragma unroll
        for (int c = 0; c < 4; c++) {
            float2 f = __half22float2(acc[r][c]);
            float v = -2.0f * (f.x + f.y);
            atomicAdd(&out[(ib + r) * ND + (jb + c)], v);
            if (tp == 1)
                atomicAdd(&out[(jb + c) * ND + (ib + r)], v);
        }
}

// ---------------------------------------------------------------- proj = subtree sums, plus S[d]
__global__ void __launch_bounds__(512)
k_proj(const float* __restrict__ mass) {
    __shared__ float s[NI];
    __shared__ float red[512];
    int d = blockIdx.x, t = threadIdx.x;
    for (int i = t; i < NI; i += 512) s[i] = 0.0f;
    __syncthreads();
    const float4* m4 = (const float4*)(mass + (size_t)d * NL);
    float msum = 0.0f;
    for (int j4 = t; j4 < NL / 4; j4 += 512) {
        float4 v = m4[j4];
        msum += v.x + v.y + v.z + v.w;
        int a0 = (int)(unsigned)(__ldg(&g_amax[4 * j4 + 0]) & 0xFFFFFFFFull);
        int a1 = (int)(unsigned)(__ldg(&g_amax[4 * j4 + 1]) & 0xFFFFFFFFull);
        int a2 = (int)(unsigned)(__ldg(&g_amax[4 * j4 + 2]) & 0xFFFFFFFFull);
        int a3 = (int)(unsigned)(__ldg(&g_amax[4 * j4 + 3]) & 0xFFFFFFFFull);
        atomicAdd(&s[a0], v.x);
        atomicAdd(&s[a1], v.y);
        atomicAdd(&s[a2], v.z);
        atomicAdd(&s[a3], v.w);
    }
    __syncthreads();
    // bottom-up tree levels: parents {156..399},{31..155},{6..30},{1..5},{0}
    const int lo[5] = {156, 31, 6, 1, 0};
    const int hi[5] = {399, 155, 30, 5, 0};
    for (int L = 0; L < 5; L++) {
        for (int p = lo[L] + t; p <= hi[L]; p += 512) {
            float acc = s[p];
            int c0 = 5 * p + 1;
            #pragma unroll
            for (int c = 0; c < 5; c++)
                if (c0 + c < NI) acc += s[c0 + c];
            s[p] = acc;
        }
        __syncthreads();
    }
    float psum = 0.0f;
    for (int i = t; i < NI; i += 512) psum += s[i];
    red[t] = msum + psum;
    __syncthreads();
    for (int w = 256; w > 0; w >>= 1) {
        if (t < w) red[t] += red[t + w];
        __syncthreads();
    }
    if (t == 0) g_S[d] = red[0];
    float* gp = g_proj + (size_t)d * PP;
    for (int i = t; i < PP; i += 512)
        gp[i] = (i < NI) ? s[i] : 0.0f;
}

// ---------------------------------------------------------------- fp32 proj-pair (64x64 tiles, 4x4 micro) || S epilogue
__global__ void __launch_bounds__(256)
k_projpair(float* __restrict__ out) {
    __shared__ float sa[PFC * SROW4];
    __shared__ float sb[PFC * SROW4];
    if (blockIdx.x < PP_BLKS) {
        int pid = blockIdx.x;
        int tp = pid % 3;                 // 0:(0,0) 1:(0,1)+mirror 2:(1,1)
        int fb = (pid / 3) * PFC;
        int it = (tp == 2) ? 1 : 0;
        int jt = (tp == 0) ? 0 : 1;
        int tid = threadIdx.x;

        #pragma unroll
        for (int k = 0; k < 8; k++) {
            int idx = tid + k * 256;          // 0..2047
            int f = idx & 31;                 // consecutive tid -> consecutive f
            int row = idx >> 5;               // 0..63
            sa[f * SROW4 + row] = g_proj[(size_t)(it * 64 + row) * PP + fb + f];
            sb[f * SROW4 + row] = g_proj[(size_t)(jt * 64 + row) * PP + fb + f];
        }
        __syncthreads();

        int tx = tid & 15, ty = tid >> 4;
        float acc[4][4];
        #pragma unroll
        for (int r = 0; r < 4; r++)
            #pragma unroll
            for (int c = 0; c < 4; c++) acc[r][c] = 0.0f;

        #pragma unroll 4
        for (int f = 0; f < PFC; f++) {
            float4 a = *(const float4*)&sa[f * SROW4 + ty * 4];
            float4 b = *(const float4*)&sb[f * SROW4 + tx * 4];
            float ar[4] = {a.x, a.y, a.z, a.w};
            float br[4] = {b.x, b.y, b.z, b.w};
            #pragma unroll
            for (int r = 0; r < 4; r++)
                #pragma unroll
                for (int c = 0; c < 4; c++)
                    acc[r][c] += fminf(ar[r], br[c]);
        }

        int ib = it * 64 + ty * 4, jb = jt * 64 + tx * 4;
        #pragma unroll
        for (int r = 0; r < 4; r++)
            #pragma unroll
            for (int c = 0; c < 4; c++) {
                float v = -2.0f * acc[r][c];
                atomicAdd(&out[(ib + r) * ND + (jb + c)], v);
                if (tp == 1)
                    atomicAdd(&out[(jb + c) * ND + (ib + r)], v);
            }
    } else {
        int e = (blockIdx.x - PP_BLKS) * 256 + threadIdx.x;  // 0..16383
        atomicAdd(&out[e], g_S[e >> 7] + g_S[e & 127]);
    }
}

// ---------------------------------------------------------------- launch (stream-forked graph)
extern "C" void kernel_launch(void* const* d_in, const int* in_sizes, int n_in,
                              void* d_out, int out_size) {
    const float* mass  = (const float*)d_in[0];   // (128, 10000) f32
    const float* param = (const float*)d_in[1];   // (2000, 10000) f32
    float* out = (float*)d_out;                   // (128, 128) f32

    // side stream + events, created once (host objects only; no device memory)
    static cudaStream_t s2 = nullptr;
    static cudaEvent_t evA = nullptr, evB = nullptr;
    if (!s2) {
        cudaStreamCreateWithFlags(&s2, cudaStreamNonBlocking);
        cudaEventCreateWithFlags(&evA, cudaEventDisableTiming);
        cudaEventCreateWithFlags(&evB, cudaEventDisableTiming);
    }

    k_init<<<64, 256>>>(out);

    // fork: mass-pair runs concurrently with argmax -> proj -> projpair
    cudaEventRecord(evA, 0);
    cudaStreamWaitEvent(s2, evA, 0);
    k_masspair<<<MP_BLKS, 256, 0, s2>>>(mass, out);

    k_argmax<<<AG_BLKS, 256>>>(param);
    k_proj<<<ND, 512>>>(mass);
    k_projpair<<<PP_BLKS + (ND * ND) / 256, 256>>>(out);

    // join
    cudaEventRecord(evB, s2);
    cudaStreamWaitEvent(0, evB, 0);
}

// round 7
// speedup vs baseline: 1.0230x; 1.0230x over previous
#include <cuda_runtime.h>
#include <cuda_fp16.h>

#define NI 2000      // inner tree nodes
#define NL 10000     // leaves / vocab
#define ND 128       // docs
#define PP 2048      // padded proj width
#define FC 64        // mass feature chunk
#define NMASS_CH 157 // ceil(NL/FC)
#define AG_BLKS 200  // argmax: 10 float4-col blocks x 20 row-chunks
#define AG_CH 100    // rows per argmax chunk
#define MP_BLKS (3 * NMASS_CH)   // 471 mass-pair blocks
#define SROWH 68     // half2 row stride per feature-pair
// proj scatter: 4 leaf-slices per doc
#define NSL 4
#define SLLEN (NL / NSL / 4)     // 625 float4 per slice
// proj-pair: 64x64 doc tiles, 32-feature chunks, 4x4 micro-tile
#define PFC 32
#define SROW4 68
#define PP_BLKS (3 * (PP / PFC))   // 192

__device__ unsigned long long g_amax[NL];
__device__ float g_proj[ND * PP];
__device__ float g_S[ND];

__device__ __forceinline__ __half2 u2h2(unsigned u) {
    return *reinterpret_cast<__half2*>(&u);
}
__device__ __forceinline__ unsigned long long pack_key(float v, int idx) {
    unsigned u = __float_as_uint(v);
    u = (u & 0x80000000u) ? ~u : (u | 0x80000000u);
    return ((unsigned long long)u << 32) | (unsigned)idx;
}

// ---------------------------------------------------------------- init
__global__ void k_init(float* __restrict__ out) {
    int i = blockIdx.x * blockDim.x + threadIdx.x;
    if (i < ND * PP) g_proj[i] = 0.0f;
    if (i < NL) g_amax[i] = 0ull;
    if (i < ND * ND) out[i] = 0.0f;
    if (i < ND) g_S[i] = 0.0f;
}

// ---------------------------------------------------------------- fused: float4 argmax || fp16 mass-pair
__global__ void __launch_bounds__(256)
k_fused1(const float* __restrict__ mass, const float* __restrict__ param,
         float* __restrict__ out) {
    __shared__ __half2 sa2[32 * SROWH];
    __shared__ __half2 sb2[32 * SROWH];

    if (blockIdx.x < AG_BLKS) {
        // ---- column argmax of param: float4 loads, 4 lane-chains ----
        int bid = blockIdx.x;
        int j4 = (bid % 10) * 256 + threadIdx.x;    // float4 column
        if (j4 >= NL / 4) return;
        int r0 = (bid / 10) * AG_CH;
        const float4* p = (const float4*)param + (size_t)r0 * (NL / 4) + j4;
        float4 bv = p[0];
        int ix = r0, iy = r0, iz = r0, iw = r0;
        #pragma unroll 4
        for (int r = 1; r < AG_CH; r++) {
            float4 v = p[(size_t)r * (NL / 4)];
            if (v.x > bv.x) { bv.x = v.x; ix = r0 + r; }
            if (v.y > bv.y) { bv.y = v.y; iy = r0 + r; }
            if (v.z > bv.z) { bv.z = v.z; iz = r0 + r; }
            if (v.w > bv.w) { bv.w = v.w; iw = r0 + r; }
        }
        int j = 4 * j4;
        atomicMax(&g_amax[j + 0], pack_key(bv.x, ix));
        atomicMax(&g_amax[j + 1], pack_key(bv.y, iy));
        atomicMax(&g_amax[j + 2], pack_key(bv.z, iz));
        atomicMax(&g_amax[j + 3], pack_key(bv.w, iw));
    } else {
        // ---- fp16 mass-pair: one 64-feature chunk, one 64x64 tile-pair ----
        int pid = blockIdx.x - AG_BLKS;
        int tp = pid % 3;                 // 0:(0,0) 1:(0,1)+mirror 2:(1,1)
        int chunk = pid / 3;
        int fb = chunk * FC;
        int nh = min(FC, NL - fb) >> 1;   // valid half2 feature-pairs
        int it = (tp == 2) ? 1 : 0;
        int jt = (tp == 0) ? 0 : 1;
        int tid = threadIdx.x;

        const __half2 hz = __float2half2_rn(0.0f);
        #pragma unroll
        for (int k = 0; k < 8; k++) {
            int idx = tid + k * 256;          // 0..2047
            int f2 = idx & 31;
            int row = idx >> 5;               // 0..63
            __half2 ha = hz, hb = hz;
            if (f2 < nh) {
                float2 va = *(const float2*)&mass[(size_t)(it * 64 + row) * NL + fb + 2 * f2];
                float2 vb = *(const float2*)&mass[(size_t)(jt * 64 + row) * NL + fb + 2 * f2];
                ha = __floats2half2_rn(va.x, va.y);
                hb = __floats2half2_rn(vb.x, vb.y);
            }
            sa2[f2 * SROWH + row] = ha;
            sb2[f2 * SROWH + row] = hb;
        }
        __syncthreads();

        int tx = tid & 15, ty = tid >> 4;
        __half2 acc[4][4];
        #pragma unroll
        for (int r = 0; r < 4; r++)
            #pragma unroll
            for (int c = 0; c < 4; c++) acc[r][c] = hz;

        #pragma unroll 4
        for (int f2 = 0; f2 < 32; f2++) {
            uint4 ua = *(const uint4*)&sa2[f2 * SROWH + ty * 4];
            uint4 ub = *(const uint4*)&sb2[f2 * SROWH + tx * 4];
            __half2 ar[4] = {u2h2(ua.x), u2h2(ua.y), u2h2(ua.z), u2h2(ua.w)};
            __half2 br[4] = {u2h2(ub.x), u2h2(ub.y), u2h2(ub.z), u2h2(ub.w)};
            #pragma unroll
            for (int r = 0; r < 4; r++)
                #pragma unroll
                for (int c = 0; c < 4; c++)
                    acc[r][c] = __hadd2(acc[r][c], __hmin2(ar[r], br[c]));
        }

        int ib = it * 64 + ty * 4, jb = jt * 64 + tx * 4;
        #pragma unroll
        for (int r = 0; r < 4; r++)
            #pragma unroll
            for (int c = 0; c < 4; c++) {
                float2 f = __half22float2(acc[r][c]);
                float v = -2.0f * (f.x + f.y);
                atomicAdd(&out[(ib + r) * ND + (jb + c)], v);
                if (tp == 1)
                    atomicAdd(&out[(jb + c) * ND + (ib + r)], v);
            }
    }
}

// ---------------------------------------------------------------- proj scatter + per-slice tree-sum
// grid (NSL, ND): each block scatters one leaf-slice of one doc into shared,
// tree-sums its partial (linear op => slices sum correctly), REDG-adds into g_proj.
__global__ void __launch_bounds__(256)
k_scatter(const float* __restrict__ mass) {
    __shared__ float s[NI];
    __shared__ float red[256];
    int sl = blockIdx.x, d = blockIdx.y, t = threadIdx.x;
    for (int i = t; i < NI; i += 256) s[i] = 0.0f;
    __syncthreads();
    const float4* m4 = (const float4*)(mass + (size_t)d * NL);
    float msum = 0.0f;
    int base = sl * SLLEN;
    for (int j4 = base + t; j4 < base + SLLEN; j4 += 256) {
        float4 v = m4[j4];
        msum += v.x + v.y + v.z + v.w;
        int a0 = (int)(unsigned)(__ldg(&g_amax[4 * j4 + 0]) & 0xFFFFFFFFull);
        int a1 = (int)(unsigned)(__ldg(&g_amax[4 * j4 + 1]) & 0xFFFFFFFFull);
        int a2 = (int)(unsigned)(__ldg(&g_amax[4 * j4 + 2]) & 0xFFFFFFFFull);
        int a3 = (int)(unsigned)(__ldg(&g_amax[4 * j4 + 3]) & 0xFFFFFFFFull);
        atomicAdd(&s[a0], v.x);
        atomicAdd(&s[a1], v.y);
        atomicAdd(&s[a2], v.z);
        atomicAdd(&s[a3], v.w);
    }
    __syncthreads();
    // bottom-up tree levels: parents {156..399},{31..155},{6..30},{1..5},{0}
    const int lo[5] = {156, 31, 6, 1, 0};
    const int hi[5] = {399, 155, 30, 5, 0};
    for (int L = 0; L < 5; L++) {
        for (int p = lo[L] + t; p <= hi[L]; p += 256) {
            float acc = s[p];
            int c0 = 5 * p + 1;
            #pragma unroll
            for (int c = 0; c < 5; c++)
                if (c0 + c < NI) acc += s[c0 + c];
            s[p] = acc;
        }
        __syncthreads();
    }
    // add slice contribution to g_proj and S[d]
    float psum = 0.0f;
    float* gp = g_proj + (size_t)d * PP;
    for (int i = t; i < NI; i += 256) {
        float val = s[i];
        psum += val;
        atomicAdd(&gp[i], val);
    }
    red[t] = msum + psum;
    __syncthreads();
    for (int w = 128; w > 0; w >>= 1) {
        if (t < w) red[t] += red[t + w];
        __syncthreads();
    }
    if (t == 0) atomicAdd(&g_S[d], red[0]);
}

// ---------------------------------------------------------------- fp32 proj-pair (64x64 tiles, 4x4 micro) || S epilogue
__global__ void __launch_bounds__(256)
k_projpair(float* __restrict__ out) {
    __shared__ float sa[PFC * SROW4];
    __shared__ float sb[PFC * SROW4];
    if (blockIdx.x < PP_BLKS) {
        int pid = blockIdx.x;
        int tp = pid % 3;                 // 0:(0,0) 1:(0,1)+mirror 2:(1,1)
        int fb = (pid / 3) * PFC;
        int it = (tp == 2) ? 1 : 0;
        int jt = (tp == 0) ? 0 : 1;
        int tid = threadIdx.x;

        #pragma unroll
        for (int k = 0; k < 8; k++) {
            int idx = tid + k * 256;          // 0..2047
            int f = idx & 31;
            int row = idx >> 5;               // 0..63
            sa[f * SROW4 + row] = g_proj[(size_t)(it * 64 + row) * PP + fb + f];
            sb[f * SROW4 + row] = g_proj[(size_t)(jt * 64 + row) * PP + fb + f];
        }
        __syncthreads();

        int tx = tid & 15, ty = tid >> 4;
        float acc[4][4];
        #pragma unroll
        for (int r = 0; r < 4; r++)
            #pragma unroll
            for (int c = 0; c < 4; c++) acc[r][c] = 0.0f;

        #pragma unroll 4
        for (int f = 0; f < PFC; f++) {
            float4 a = *(const float4*)&sa[f * SROW4 + ty * 4];
            float4 b = *(const float4*)&sb[f * SROW4 + tx * 4];
            float ar[4] = {a.x, a.y, a.z, a.w};
            float br[4] = {b.x, b.y, b.z, b.w};
            #pragma unroll
            for (int r = 0; r < 4; r++)
                #pragma unroll
                for (int c = 0; c < 4; c++)
                    acc[r][c] += fminf(ar[r], br[c]);
        }

        int ib = it * 64 + ty * 4, jb = jt * 64 + tx * 4;
        #pragma unroll
        for (int r = 0; r < 4; r++)
            #pragma unroll
            for (int c = 0; c < 4; c++) {
                float v = -2.0f * acc[r][c];
                atomicAdd(&out[(ib + r) * ND + (jb + c)], v);
                if (tp == 1)
                    atomicAdd(&out[(jb + c) * ND + (ib + r)], v);
            }
    } else {
        int e = (blockIdx.x - PP_BLKS) * 256 + threadIdx.x;  // 0..16383
        atomicAdd(&out[e], g_S[e >> 7] + g_S[e & 127]);
    }
}

// ---------------------------------------------------------------- launch (single stream)
extern "C" void kernel_launch(void* const* d_in, const int* in_sizes, int n_in,
                              void* d_out, int out_size) {
    const float* mass  = (const float*)d_in[0];   // (128, 10000) f32
    const float* param = (const float*)d_in[1];   // (2000, 10000) f32
    float* out = (float*)d_out;                   // (128, 128) f32

    k_init<<<(ND * PP + 255) / 256, 256>>>(out);
    k_fused1<<<AG_BLKS + MP_BLKS, 256>>>(mass, param, out);
    k_scatter<<<dim3(NSL, ND), 256>>>(mass);
    k_projpair<<<PP_BLKS + (ND * ND) / 256, 256>>>(out);
}